// round 17
// baseline (speedup 1.0000x reference)
#include <cuda_runtime.h>
#include <cuda_bf16.h>
#include <cstdint>

// Problem constants
#define Bz 4
#define Sz 1024
#define Dz 512
#define Hz 8
#define DKz 64
#define Lz 4
#define DFFz 2048
#define SOFTCAP 30.0f
#define PAD_IDX 0
#define START_IDX 1

#define ROWS (Bz*Sz)           // 4096
#define XSZ  (ROWS*Dz)         // 2,097,152
#define H1SZ (ROWS*DFFz)       // 8,388,608
#define DD   (Dz*Dz)
#define DF   (Dz*DFFz)

#define OFF_WQ 0
#define OFF_WK (4*DD)
#define OFF_WV (8*DD)
#define OFF_WO (12*DD)
#define OFF_W1 (16*DD)
#define OFF_W2 (16*DD + 4*DF)
#define WT_TOT (16*DD + 8*DF)

// Persistent scratch
__device__ float g_x[XSZ];
__device__ float g_xn[XSZ];
__device__ float g_k[XSZ];
__device__ float g_v[XSZ];
__device__ float g_cb[ROWS];
__device__ int   g_keep[ROWS];
__device__ __align__(16) __nv_bfloat16 g_wth[WT_TOT];
__device__ __align__(16) __nv_bfloat16 g_wtl[WT_TOT];
__device__ __align__(16) __nv_bfloat16 g_xnh[XSZ], g_xnl[XSZ];
__device__ __align__(16) __nv_bfloat16 g_qh[XSZ],  g_ql[XSZ];
__device__ __align__(16) __nv_bfloat16 g_kh[XSZ],  g_kl[XSZ];
__device__ __align__(16) __nv_bfloat16 g_vh[XSZ],  g_vl[XSZ];
__device__ __align__(16) __nv_bfloat16 g_oh[XSZ],  g_ol[XSZ];
__device__ __align__(16) __nv_bfloat16 g_h1h[H1SZ], g_h1l[H1SZ];

// ---------------------------------------------------------------------------
// helpers
// ---------------------------------------------------------------------------
__device__ __forceinline__ void bsplit(float x, __nv_bfloat16& h, __nv_bfloat16& l)
{
    h = __float2bfloat16_rn(x);
    l = __float2bfloat16_rn(x - __bfloat162float(h));
}
__device__ __forceinline__ uint32_t bpack(__nv_bfloat16 a, __nv_bfloat16 b)
{
    uint16_t ua = *reinterpret_cast<uint16_t*>(&a);
    uint16_t ub = *reinterpret_cast<uint16_t*>(&b);
    return (uint32_t)ua | ((uint32_t)ub << 16);
}
__device__ __forceinline__ void psplit2(float x, float y, uint32_t& h, uint32_t& l)
{
    __nv_bfloat16 hx, lx, hy, ly;
    bsplit(x, hx, lx); bsplit(y, hy, ly);
    h = bpack(hx, hy); l = bpack(lx, ly);
}
__device__ __forceinline__ float gelu_fast(float x)
{
    float t = 0.7978845608028654f * (x + 0.044715f * x * x * x);
    float e = __expf(2.f * t);
    return x - x * __fdividef(1.f, e + 1.f);
}

#define MMA_BF16(d, a0, a1, a2, a3, b0, b1) \
    asm volatile("mma.sync.aligned.m16n8k16.row.col.f32.bf16.bf16.f32 " \
        "{%0,%1,%2,%3},{%4,%5,%6,%7},{%8,%9},{%0,%1,%2,%3};" \
        : "+f"(d[0]), "+f"(d[1]), "+f"(d[2]), "+f"(d[3]) \
        : "r"(a0), "r"(a1), "r"(a2), "r"(a3), "r"(b0), "r"(b1))

#define LDSM4(r, addr) \
    asm volatile("ldmatrix.sync.aligned.m8n8.x4.shared.b16 {%0,%1,%2,%3},[%4];" \
        : "=r"((r)[0]), "=r"((r)[1]), "=r"((r)[2]), "=r"((r)[3]) : "r"(addr))
#define LDSM4T(r, addr) \
    asm volatile("ldmatrix.sync.aligned.m8n8.x4.trans.shared.b16 {%0,%1,%2,%3},[%4];" \
        : "=r"((r)[0]), "=r"((r)[1]), "=r"((r)[2]), "=r"((r)[3]) : "r"(addr))

__device__ __forceinline__ void cp16(uint32_t dst, const void* src)
{
    uint64_t g = (uint64_t)__cvta_generic_to_global(src);
    asm volatile("cp.async.cg.shared.global [%0], [%1], 16;" :: "r"(dst), "l"(g));
}
#define CP_COMMIT() asm volatile("cp.async.commit_group;")
#define CP_WAIT1()  asm volatile("cp.async.wait_group 1;")
#define CP_WAIT0()  asm volatile("cp.async.wait_group 0;")

// ---------------------------------------------------------------------------
// Embedding
// ---------------------------------------------------------------------------
__global__ void embed_kernel(const int* __restrict__ tok,
                             const float* __restrict__ cnt,
                             const float* __restrict__ emb)
{
    int r = blockIdx.x;
    int b = r / Sz, s = r % Sz;
    int t; float c;
    if (s == 0) { t = START_IDX; c = 1.0f; }
    else        { t = tok[b*Sz + s - 1]; c = cnt[b*Sz + s - 1]; }
    if (threadIdx.x == 0) {
        g_cb[r]   = log1pf(c + 1e-6f);
        g_keep[r] = (t != PAD_IDX);
    }
    const float4* src = (const float4*)(emb + (size_t)t * Dz);
    float4* dst = (float4*)(g_x + (size_t)r * Dz);
    dst[threadIdx.x] = src[threadIdx.x];
}

// ---------------------------------------------------------------------------
// Merged weight transpose + bf16 split: ALL weights in ONE launch.
// ---------------------------------------------------------------------------
__global__ void tsplit_all_kernel(const float* __restrict__ Wq, const float* __restrict__ Wk,
                                  const float* __restrict__ Wv, const float* __restrict__ Wo,
                                  const float* __restrict__ W1, const float* __restrict__ W2,
                                  __nv_bfloat16* __restrict__ dh_base,
                                  __nv_bfloat16* __restrict__ dl_base)
{
    __shared__ float t[32][33];
    int bid = blockIdx.x;
    const float* src; size_t doff; int K, N, n0, k0;
    if (bid < 4096) {
        int w = bid >> 10, r = bid & 1023;
        int layer = r >> 8, tt = r & 255;
        src  = ((w == 0) ? Wq : (w == 1) ? Wk : (w == 2) ? Wv : Wo) + (size_t)layer * DD;
        doff = (size_t)w * 4 * DD + (size_t)layer * DD;
        K = Dz; N = Dz;
        n0 = (tt & 15) * 32; k0 = (tt >> 4) * 32;
    } else if (bid < 8192) {
        int r = bid - 4096, layer = r >> 10, tt = r & 1023;
        src  = W1 + (size_t)layer * DF;
        doff = (size_t)OFF_W1 + (size_t)layer * DF;
        K = Dz; N = DFFz;
        n0 = (tt & 63) * 32; k0 = (tt >> 6) * 32;
    } else {
        int r = bid - 8192, layer = r >> 10, tt = r & 1023;
        src  = W2 + (size_t)layer * DF;
        doff = (size_t)OFF_W2 + (size_t)layer * DF;
        K = DFFz; N = Dz;
        n0 = (tt & 15) * 32; k0 = (tt >> 4) * 32;
    }
    __nv_bfloat16* dh = dh_base + doff;
    __nv_bfloat16* dl = dl_base + doff;
    int tx = threadIdx.x & 31, ty = threadIdx.x >> 5;
    #pragma unroll
    for (int i = 0; i < 4; i++)
        t[ty + 8*i][tx] = src[(size_t)(k0 + ty + 8*i) * N + n0 + tx];
    __syncthreads();
    #pragma unroll
    for (int i = 0; i < 4; i++) {
        float v = t[tx][ty + 8*i];
        __nv_bfloat16 h, l; bsplit(v, h, l);
        size_t idx = (size_t)(n0 + ty + 8*i) * K + k0 + tx;
        dh[idx] = h; dl[idx] = l;
    }
}

// ---------------------------------------------------------------------------
// LayerNorm -> fp32 + bf16 hi/lo
// ---------------------------------------------------------------------------
__device__ __forceinline__ float block_reduce_sum(float v, float* red)
{
    int lane = threadIdx.x & 31, warp = threadIdx.x >> 5;
    #pragma unroll
    for (int o = 16; o > 0; o >>= 1) v += __shfl_xor_sync(0xffffffffu, v, o);
    if (lane == 0) red[warp] = v;
    __syncthreads();
    float r = 0.f;
    if (warp == 0) {
        r = (lane < (blockDim.x >> 5)) ? red[lane] : 0.f;
        #pragma unroll
        for (int o = 16; o > 0; o >>= 1) r += __shfl_xor_sync(0xffffffffu, r, o);
        if (lane == 0) red[0] = r;
    }
    __syncthreads();
    r = red[0];
    __syncthreads();
    return r;
}

__global__ void layernorm_kernel(const float* __restrict__ x,
                                 const float* __restrict__ gam,
                                 const float* __restrict__ bet,
                                 float* __restrict__ out,
                                 __nv_bfloat16* __restrict__ outh,
                                 __nv_bfloat16* __restrict__ outl)
{
    __shared__ float red[32];
    int r = blockIdx.x;
    const float4* xr = (const float4*)(x + (size_t)r * Dz);
    float4 v = xr[threadIdx.x];
    float s = v.x + v.y + v.z + v.w;
    float tot = block_reduce_sum(s, red);
    float mu = tot * (1.0f / Dz);
    float d0 = v.x - mu, d1 = v.y - mu, d2 = v.z - mu, d3 = v.w - mu;
    float sq = d0*d0 + d1*d1 + d2*d2 + d3*d3;
    float var = block_reduce_sum(sq, red) * (1.0f / Dz);
    float rstd = rsqrtf(var + 1e-5f);
    float4 gg = ((const float4*)gam)[threadIdx.x];
    float4 bb = ((const float4*)bet)[threadIdx.x];
    float4 o;
    o.x = d0 * rstd * gg.x + bb.x;
    o.y = d1 * rstd * gg.y + bb.y;
    o.z = d2 * rstd * gg.z + bb.z;
    o.w = d3 * rstd * gg.w + bb.w;
    ((float4*)(out + (size_t)r * Dz))[threadIdx.x] = o;
    uint32_t h0, l0, h1, l1;
    psplit2(o.x, o.y, h0, l0);
    psplit2(o.z, o.w, h1, l1);
    uint2 ph = { h0, h1 }, pl = { l0, l1 };
    *(uint2*)(outh + (size_t)r * Dz + threadIdx.x * 4) = ph;
    *(uint2*)(outl + (size_t)r * Dz + threadIdx.x * 4) = pl;
}

// ---------------------------------------------------------------------------
// GEMM v6: bf16 3-term split, BK=32, 2-stage double buffer,
// 128 threads / 4 warps, warp tile 64x64 (16 LDSM : 96 MMA per warp-k16
// -> smem bytes per MMA cut 1.5x; smem-BW bound 1536->1024 cyc/iter).
// Stage layout identical to v5b (stride 80, conflict-free, 16B-aligned).
// __launch_bounds__(128,2) -> 2 CTAs/SM (164KB smem, 8 warps/SM).
// ---------------------------------------------------------------------------
#define GARR   10240                // 128 * 80
#define GSTAGE (4 * GARR)           // 40960
#define GSMEM  (2 * GSTAGE)         // 81920

__device__ __forceinline__ void stage_load(
    uint32_t smem_u32, int s, int k0, int K,
    const __nv_bfloat16* Ah, const __nv_bfloat16* Al,
    const __nv_bfloat16* Bh, const __nv_bfloat16* Bl,
    int aBase, int bBase, int tid)
{
    #pragma unroll
    for (int rep = 0; rep < 16; rep++) {
        int c = tid + rep * 128;          // 0..2047
        int arr = c >> 9;                 // 0..3
        int rem = c & 511;
        int r = rem >> 2, h = rem & 3;    // row 0..127, 16B-chunk 0..3
        const __nv_bfloat16* g =
            (arr == 0) ? Ah + (size_t)(aBase + r) * K :
            (arr == 1) ? Al + (size_t)(aBase + r) * K :
            (arr == 2) ? Bh + (size_t)(bBase + r) * K :
                         Bl + (size_t)(bBase + r) * K;
        uint32_t dst = smem_u32 + s * GSTAGE + arr * GARR + r * 80 + h * 16;
        cp16(dst, g + k0 + h * 8);
    }
}

template<int EPI>
__device__ __forceinline__ void gemm3_body(
    int M, int N, int K,
    const __nv_bfloat16* __restrict__ Ah, const __nv_bfloat16* __restrict__ Al,
    const __nv_bfloat16* __restrict__ Bh, const __nv_bfloat16* __restrict__ Bl,
    const float* __restrict__ bias, const float* __restrict__ res,
    float* __restrict__ C, __nv_bfloat16* __restrict__ Ch,
    __nv_bfloat16* __restrict__ Cl, bool outbf, int bx, int by)
{
    extern __shared__ __align__(16) char smraw[];
    uint32_t smem_u32 = (uint32_t)__cvta_generic_to_shared(smraw);
    int tid = threadIdx.x;
    int lane = tid & 31, warp = tid >> 5;     // 4 warps
    int wm = warp >> 1, wn = warp & 1;        // 2x2 warps, tile 64x64
    int gid = lane >> 2, tig = lane & 3;
    int aBase = by * 128, bBase = bx * 128;

    float acc[4][8][4];
    #pragma unroll
    for (int mt = 0; mt < 4; mt++)
        #pragma unroll
        for (int nt = 0; nt < 8; nt++)
            #pragma unroll
            for (int i = 0; i < 4; i++) acc[mt][nt][i] = 0.f;

    int nIter = K / 32;
    stage_load(smem_u32, 0, 0, K, Ah, Al, Bh, Bl, aBase, bBase, tid);
    CP_COMMIT();

    uint32_t aoff = (uint32_t)((wm*64 + (lane & 15)) * 80 + (lane >> 4) * 16);
    int brow = wn*64 + ((lane & 7) | (((lane >> 4) & 1) << 3));
    uint32_t boff = (uint32_t)(brow * 80 + ((lane >> 3) & 1) * 16);

    int stg = 0;
    for (int it = 0; it < nIter; it++) {
        CP_WAIT0();
        __syncthreads();
        if (it + 1 < nIter) {
            stage_load(smem_u32, stg ^ 1, (it + 1) * 32, K, Ah, Al, Bh, Bl,
                       aBase, bBase, tid);
            CP_COMMIT();
        }

        uint32_t sb = smem_u32 + stg * GSTAGE;
        #pragma unroll
        for (int ks = 0; ks < 2; ks++) {
            uint32_t kso = (uint32_t)(ks * 32);
            uint32_t bh[4][4], bl[4][4];
            #pragma unroll
            for (int g = 0; g < 4; g++) {
                LDSM4(bh[g], sb + 2*GARR + boff + kso + (uint32_t)(g * 1280));
                LDSM4(bl[g], sb + 3*GARR + boff + kso + (uint32_t)(g * 1280));
            }

            #pragma unroll
            for (int mt = 0; mt < 4; mt++) {
                uint32_t ah[4], al[4];
                LDSM4(ah, sb + aoff + kso + (uint32_t)(mt * 1280));
                LDSM4(al, sb + GARR + aoff + kso + (uint32_t)(mt * 1280));
                #pragma unroll
                for (int nt = 0; nt < 8; nt++) {
                    int g = nt >> 1, q = (nt & 1) * 2;
                    MMA_BF16(acc[mt][nt], ah[0], ah[1], ah[2], ah[3],
                             bh[g][q], bh[g][q+1]);
                    MMA_BF16(acc[mt][nt], ah[0], ah[1], ah[2], ah[3],
                             bl[g][q], bl[g][q+1]);
                    MMA_BF16(acc[mt][nt], al[0], al[1], al[2], al[3],
                             bh[g][q], bh[g][q+1]);
                }
            }
        }
        stg ^= 1;
    }

    size_t rowBase = (size_t)by * 128 + wm * 64;
    size_t colBase = (size_t)bx * 128 + wn * 64;
    #pragma unroll
    for (int nt = 0; nt < 8; nt++) {
        size_t c = colBase + nt * 8 + tig * 2;
        float2 bb = *(const float2*)(bias + c);
        #pragma unroll
        for (int mt = 0; mt < 4; mt++) {
            size_t r0 = rowBase + mt * 16 + gid;
            size_t r1 = r0 + 8;
            float2 v0, v1;
            v0.x = acc[mt][nt][0] + bb.x; v0.y = acc[mt][nt][1] + bb.y;
            v1.x = acc[mt][nt][2] + bb.x; v1.y = acc[mt][nt][3] + bb.y;
            if (EPI == 1) {
                v0.x = gelu_fast(v0.x); v0.y = gelu_fast(v0.y);
                v1.x = gelu_fast(v1.x); v1.y = gelu_fast(v1.y);
            }
            if (EPI == 2) {
                float2 q0 = *(const float2*)(res + r0 * N + c);
                float2 q1 = *(const float2*)(res + r1 * N + c);
                v0.x += q0.x; v0.y += q0.y;
                v1.x += q1.x; v1.y += q1.y;
            }
            if (outbf) {
                uint32_t h, l;
                psplit2(v0.x, v0.y, h, l);
                *(uint32_t*)(Ch + r0 * N + c) = h;
                *(uint32_t*)(Cl + r0 * N + c) = l;
                psplit2(v1.x, v1.y, h, l);
                *(uint32_t*)(Ch + r1 * N + c) = h;
                *(uint32_t*)(Cl + r1 * N + c) = l;
            } else {
                *(float2*)(C + r0 * N + c) = v0;
                *(float2*)(C + r1 * N + c) = v1;
            }
        }
    }
}

template<int EPI>
__global__ void __launch_bounds__(128, 2)
gemm3_kernel(int M, int N, int K,
             const __nv_bfloat16* Ah, const __nv_bfloat16* Al,
             const __nv_bfloat16* Bh, const __nv_bfloat16* Bl,
             const float* bias, const float* res,
             float* C, __nv_bfloat16* Ch, __nv_bfloat16* Cl, int outbf)
{
    gemm3_body<EPI>(M, N, K, Ah, Al, Bh, Bl, bias, res, C, Ch, Cl, outbf != 0,
                    blockIdx.x, blockIdx.y);
}

__global__ void __launch_bounds__(128, 2)
qkv3_kernel(const __nv_bfloat16* Ah, const __nv_bfloat16* Al,
            const __nv_bfloat16* WqH, const __nv_bfloat16* WqL,
            const __nv_bfloat16* WkH, const __nv_bfloat16* WkL,
            const __nv_bfloat16* WvH, const __nv_bfloat16* WvL,
            const float* bq, const float* bk, const float* bv,
            __nv_bfloat16* Cqh, __nv_bfloat16* Cql,
            float* Ck, float* Cv)
{
    int which = blockIdx.x >> 2;
    int bx = blockIdx.x & 3;
    const __nv_bfloat16* Bh = (which == 0) ? WqH : (which == 1) ? WkH : WvH;
    const __nv_bfloat16* Bl = (which == 0) ? WqL : (which == 1) ? WkL : WvL;
    const float* b = (which == 0) ? bq : (which == 1) ? bk : bv;
    float* C = (which == 1) ? Ck : Cv;
    gemm3_body<0>(ROWS, Dz, Dz, Ah, Al, Bh, Bl, b, nullptr, C, Cqh, Cql,
                  which == 0, bx, blockIdx.y);
}

// ---------------------------------------------------------------------------
// quant-dequant: fp32 in -> bf16 hi/lo out
// ---------------------------------------------------------------------------
__global__ void quantdq_kernel(const float* __restrict__ tk, const float* __restrict__ tv,
                               __nv_bfloat16* __restrict__ okh, __nv_bfloat16* __restrict__ okl,
                               __nv_bfloat16* __restrict__ ovh, __nv_bfloat16* __restrict__ ovl,
                               const float* __restrict__ lvk,
                               const float* __restrict__ lvv)
{
    __shared__ float lv[8];
    const float* t = (blockIdx.y == 0) ? tk : tv;
    __nv_bfloat16* oh = (blockIdx.y == 0) ? okh : ovh;
    __nv_bfloat16* ol = (blockIdx.y == 0) ? okl : ovl;
    const float* levels = (blockIdx.y == 0) ? lvk : lvv;
    if (threadIdx.x < 8) lv[threadIdx.x] = levels[threadIdx.x];
    __syncthreads();
    int warp = threadIdx.x >> 5, lane = threadIdx.x & 31;
    int w = blockIdx.x * 8 + warp;
    size_t off = (size_t)(w / Hz) * Dz + (size_t)(w % Hz) * DKz;
    const float* p = t + off;

    float x0 = p[lane], x1 = p[lane + 32];
    float ss = x0 * x0 + x1 * x1;
    #pragma unroll
    for (int o = 16; o > 0; o >>= 1) ss += __shfl_xor_sync(0xffffffffu, ss, o);
    float nrm = sqrtf(ss);
    float inv = 1.f / (nrm + 1e-8f);
    float u0 = x0 * inv, u1 = x1 * inv;
    float a0 = fabsf(u0), a1 = fabsf(u1);
    float sg0 = (u0 >= 0.f) ? 1.f : -1.f;
    float sg1 = (u1 >= 0.f) ? 1.f : -1.f;

    float q0 = lv[0], b0 = fabsf(a0 - lv[0]);
    float q1 = lv[0], b1 = fabsf(a1 - lv[0]);
    #pragma unroll
    for (int i = 1; i < 8; i++) {
        float d0 = fabsf(a0 - lv[i]);
        if (d0 < b0) { b0 = d0; q0 = lv[i]; }
        float d1 = fabsf(a1 - lv[i]);
        if (d1 < b1) { b1 = d1; q1 = lv[i]; }
    }
    float num = a0 * q0 + a1 * q1;
    float den = q0 * q0 + q1 * q1;
    #pragma unroll
    for (int o = 16; o > 0; o >>= 1) {
        num += __shfl_xor_sync(0xffffffffu, num, o);
        den += __shfl_xor_sync(0xffffffffu, den, o);
    }
    float rmag = num / (den + 1e-8f);
    float r0 = sg0 * q0 * rmag * nrm;
    float r1 = sg1 * q1 * rmag * nrm;
    __nv_bfloat16 h, l;
    bsplit(r0, h, l); oh[off + lane] = h;      ol[off + lane] = l;
    bsplit(r1, h, l); oh[off + lane + 32] = h; ol[off + lane + 32] = l;
}

// ---------------------------------------------------------------------------
// Tensor-core attention v2 (R16 passing version, unchanged)
// ---------------------------------------------------------------------------
#define AT_STRIDE 144
#define AT_TILE   (64 * AT_STRIDE)
#define AT2_Q_H   0
#define AT2_Q_L   AT_TILE
#define AT2_KV(s) (2*AT_TILE + (s)*(4*AT_TILE))
#define AT2_CB    (10*AT_TILE)
#define ATTN2_SMEM (10*AT_TILE + 1024)

__device__ __forceinline__ void at_load_kv(
    uint32_t sb, int s,
    const __nv_bfloat16* kh, const __nv_bfloat16* kl,
    const __nv_bfloat16* vh, const __nv_bfloat16* vl,
    int b, int k0, size_t hcol, int tid)
{
    #pragma unroll
    for (int i = 0; i < 16; i++) {
        int c = tid + i * 128;
        int arr = c >> 9, r = (c >> 3) & 63, ch = c & 7;
        const __nv_bfloat16* src =
            (arr == 0 ? kh : arr == 1 ? kl : arr == 2 ? vh : vl)
            + (size_t)(b * Sz + k0 + r) * Dz + hcol + ch * 8;
        cp16(sb + AT2_KV(s) + arr * AT_TILE + r * AT_STRIDE + ch * 16, src);
    }
}

__global__ void __launch_bounds__(128, 1)
attn2_kernel(const __nv_bfloat16* __restrict__ qh, const __nv_bfloat16* __restrict__ ql,
             const __nv_bfloat16* __restrict__ kh, const __nv_bfloat16* __restrict__ kl,
             const __nv_bfloat16* __restrict__ vh, const __nv_bfloat16* __restrict__ vl,
             __nv_bfloat16* __restrict__ o_hi, __nv_bfloat16* __restrict__ o_lo,
             const float* __restrict__ cb, const int* __restrict__ keep)
{
    extern __shared__ __align__(16) char sm2[];
    uint32_t sb = (uint32_t)__cvta_generic_to_shared(sm2);
    float* cbs = (float*)(sm2 + AT2_CB);
    float* mks = cbs + 128;

    int tid = threadIdx.x;
    int lane = tid & 31, warp = tid >> 5;
    int gid = lane >> 2, tig = lane & 3;
    int bh = blockIdx.y;
    int b = bh >> 3, h = bh & 7;
    size_t hcol = (size_t)h * DKz;

    uint32_t qaddr_base = (uint32_t)((warp*16 + (lane & 15)) * AT_STRIDE + (lane >> 4) * 16);
    uint32_t krow_off   = (uint32_t)(((lane & 7) | (((lane >> 4) & 1) << 3)) * AT_STRIDE
                                     + ((lane >> 3) & 1) * 16);
    uint32_t vaddr_base = (uint32_t)((lane & 15) * AT_STRIDE + ((lane >> 4) << 3) * 2);

    #pragma unroll
    for (int sub = 0; sub < 2; sub++) {
        int qt = (sub == 0) ? blockIdx.x : 15 - blockIdx.x;
        int q0 = qt * 64;

        #pragma unroll
        for (int i = 0; i < 8; i++) {
            int c = tid + i * 128;
            int arr = c >> 9, r = (c >> 3) & 63, ch = c & 7;
            const __nv_bfloat16* src = (arr ? ql : qh)
                + (size_t)(b * Sz + q0 + r) * Dz + hcol + ch * 8;
            cp16(sb + (arr ? AT2_Q_L : AT2_Q_H) + r * AT_STRIDE + ch * 16, src);
        }
        CP_COMMIT();
        at_load_kv(sb, 0, kh, kl, vh, vl, b, 0, hcol, tid);
        CP_COMMIT();
        if (tid < 64) {
            cbs[tid] = cb[b * Sz + tid];
            mks[tid] = keep[b * Sz + tid] ? 1.f : 0.f;
        }

        float acc_o[8][4];
        #pragma unroll
        for (int nt = 0; nt < 8; nt++)
            #pragma unroll
            for (int i = 0; i < 4; i++) acc_o[nt][i] = 0.f;
        float den0 = 0.f, den1 = 0.f;

        for (int kt = 0; kt <= qt; kt++) {
            int stg = kt & 1;
            bool more = (kt + 1 <= qt);
            if (more) {
                at_load_kv(sb, stg ^ 1, kh, kl, vh, vl, b, (kt + 1) * 64, hcol, tid);
                CP_COMMIT();
                if (tid < 64) {
                    cbs[(stg ^ 1) * 64 + tid] = cb[b * Sz + (kt + 1) * 64 + tid];
                    mks[(stg ^ 1) * 64 + tid] = keep[b * Sz + (kt + 1) * 64 + tid] ? 1.f : 0.f;
                }
                CP_WAIT1();
            } else {
                CP_WAIT0();
            }
            __syncthreads();

            uint32_t kvb = sb + AT2_KV(stg);
            int k0 = kt * 64;
            float* cbt = cbs + stg * 64;
            float* mkt = mks + stg * 64;

            float s[8][4];
            #pragma unroll
            for (int nt = 0; nt < 8; nt++)
                #pragma unroll
                for (int i = 0; i < 4; i++) s[nt][i] = 0.f;

            #pragma unroll
            for (int ks = 0; ks < 4; ks++) {
                uint32_t qa[4], qb[4];
                LDSM4(qa, sb + AT2_Q_H + qaddr_base + ks * 32);
                LDSM4(qb, sb + AT2_Q_L + qaddr_base + ks * 32);
                uint32_t KH[4][4], KL[4][4];
                #pragma unroll
                for (int g = 0; g < 4; g++) {
                    uint32_t off = (uint32_t)(g * 16 * AT_STRIDE) + krow_off + ks * 32;
                    LDSM4(KH[g], kvb + off);
                    LDSM4(KL[g], kvb + AT_TILE + off);
                }
                #pragma unroll
                for (int nt = 0; nt < 8; nt++) {
                    int g = nt >> 1, q = (nt & 1) * 2;
                    MMA_BF16(s[nt], qa[0], qa[1], qa[2], qa[3], KH[g][q], KH[g][q+1]);
                    MMA_BF16(s[nt], qa[0], qa[1], qa[2], qa[3], KL[g][q], KL[g][q+1]);
                    MMA_BF16(s[nt], qb[0], qb[1], qb[2], qb[3], KH[g][q], KH[g][q+1]);
                }
            }

            int qrow = q0 + warp * 16 + gid;
            #pragma unroll
            for (int nt = 0; nt < 8; nt++) {
                #pragma unroll
                for (int i = 0; i < 4; i++) {
                    int kgl = nt * 8 + tig * 2 + (i & 1);
                    int qg = qrow + (i >> 1) * 8;
                    float y = s[nt][i] * 0.125f + cbt[kgl];
                    float u = __expf(y * (1.0f / 15.0f));
                    float p = __expf(30.f - __fdividef(60.f, u + 1.f)) * mkt[kgl];
                    s[nt][i] = (k0 + kgl <= qg) ? p : 0.f;
                }
            }
            #pragma unroll
            for (int nt = 0; nt < 8; nt++) {
                den0 += s[nt][0] + s[nt][1];
                den1 += s[nt][2] + s[nt][3];
            }

            #pragma unroll
            for (int j = 0; j < 4; j++) {
                uint32_t pa[4], pb[4];
                psplit2(s[2*j][0],   s[2*j][1],   pa[0], pb[0]);
                psplit2(s[2*j][2],   s[2*j][3],   pa[1], pb[1]);
                psplit2(s[2*j+1][0], s[2*j+1][1], pa[2], pb[2]);
                psplit2(s[2*j+1][2], s[2*j+1][3], pa[3], pb[3]);
                #pragma unroll
                for (int dg = 0; dg < 4; dg++) {
                    uint32_t VH4[4], VL4[4];
                    uint32_t voff = vaddr_base + (uint32_t)(j * 16 * AT_STRIDE) + dg * 32;
                    LDSM4T(VH4, kvb + 2 * AT_TILE + voff);
                    LDSM4T(VL4, kvb + 3 * AT_TILE + voff);
                    MMA_BF16(acc_o[2*dg],   pa[0], pa[1], pa[2], pa[3], VH4[0], VH4[1]);
                    MMA_BF16(acc_o[2*dg],   pa[0], pa[1], pa[2], pa[3], VL4[0], VL4[1]);
                    MMA_BF16(acc_o[2*dg],   pb[0], pb[1], pb[2], pb[3], VH4[0], VH4[1]);
                    MMA_BF16(acc_o[2*dg+1], pa[0], pa[1], pa[2], pa[3], VH4[2], VH4[3]);
                    MMA_BF16(acc_o[2*dg+1], pa[0], pa[1], pa[2], pa[3], VL4[2], VL4[3]);
                    MMA_BF16(acc_o[2*dg+1], pb[0], pb[1], pb[2], pb[3], VH4[2], VH4[3]);
                }
            }
            __syncthreads();
        }

        den0 += __shfl_xor_sync(0xffffffffu, den0, 1);
        den0 += __shfl_xor_sync(0xffffffffu, den0, 2);
        den1 += __shfl_xor_sync(0xffffffffu, den1, 1);
        den1 += __shfl_xor_sync(0xffffffffu, den1, 2);
        float i0 = __fdividef(1.f, den0);
        float i1 = __fdividef(1.f, den1);

        size_t r0 = (size_t)(b * Sz + q0 + warp * 16 + gid);
        size_t r1 = r0 + 8;
        #pragma unroll
        for (int nt = 0; nt < 8; nt++) {
            size_t c = hcol + nt * 8 + tig * 2;
            uint32_t hh, ll;
            psplit2(acc_o[nt][0] * i0, acc_o[nt][1] * i0, hh, ll);
            *(uint32_t*)(o_hi + r0 * Dz + c) = hh;
            *(uint32_t*)(o_lo + r0 * Dz + c) = ll;
            psplit2(acc_o[nt][2] * i1, acc_o[nt][3] * i1, hh, ll);
            *(uint32_t*)(o_hi + r1 * Dz + c) = hh;
            *(uint32_t*)(o_lo + r1 * Dz + c) = ll;
        }
    }
}

// ---------------------------------------------------------------------------
// Host launcher
// ---------------------------------------------------------------------------
extern "C" void kernel_launch(void* const* d_in, const int* in_sizes, int n_in,
                              void* d_out, int out_size)
{
    const int*   tok  = (const int*)  d_in[0];
    const float* cnt  = (const float*)d_in[1];
    const float* emb  = (const float*)d_in[2];
    const float* Wq   = (const float*)d_in[3];
    const float* bq   = (const float*)d_in[4];
    const float* Wk   = (const float*)d_in[5];
    const float* bk   = (const float*)d_in[6];
    const float* Wv   = (const float*)d_in[7];
    const float* bv   = (const float*)d_in[8];
    const float* Wo   = (const float*)d_in[9];
    const float* bo   = (const float*)d_in[10];
    const float* ln1g = (const float*)d_in[11];
    const float* ln1b = (const float*)d_in[12];
    const float* ln2g = (const float*)d_in[13];
    const float* ln2b = (const float*)d_in[14];
    const float* W1   = (const float*)d_in[15];
    const float* b1   = (const float*)d_in[16];
    const float* W2   = (const float*)d_in[17];
    const float* b2   = (const float*)d_in[18];
    const float* cbk  = (const float*)d_in[19];
    float* out = (float*)d_out;

    cudaFuncSetAttribute(attn2_kernel, cudaFuncAttributeMaxDynamicSharedMemorySize, ATTN2_SMEM);
    cudaFuncSetAttribute(qkv3_kernel, cudaFuncAttributeMaxDynamicSharedMemorySize, GSMEM);
    cudaFuncSetAttribute(gemm3_kernel<2>, cudaFuncAttributeMaxDynamicSharedMemorySize, GSMEM);
    cudaFuncSetAttribute(gemm3_kernel<1>, cudaFuncAttributeMaxDynamicSharedMemorySize, GSMEM);

    float *px, *pxn, *pk, *pv, *pcb;
    int *pkeep;
    __nv_bfloat16 *pwth, *pwtl, *pxnh, *pxnl, *pqh, *pql, *pkh, *pkl, *pvh, *pvl;
    __nv_bfloat16 *poh, *pol, *ph1h, *ph1l;
    cudaGetSymbolAddress((void**)&px,   g_x);
    cudaGetSymbolAddress((void**)&pxn,  g_xn);
    cudaGetSymbolAddress((void**)&pk,   g_k);
    cudaGetSymbolAddress((void**)&pv,   g_v);
    cudaGetSymbolAddress((void**)&pcb,  g_cb);
    cudaGetSymbolAddress((void**)&pkeep, g_keep);
    cudaGetSymbolAddress((void**)&pwth, g_wth);
    cudaGetSymbolAddress((void**)&pwtl, g_wtl);
    cudaGetSymbolAddress((void**)&pxnh, g_xnh);
    cudaGetSymbolAddress((void**)&pxnl, g_xnl);
    cudaGetSymbolAddress((void**)&pqh,  g_qh);
    cudaGetSymbolAddress((void**)&pql,  g_ql);
    cudaGetSymbolAddress((void**)&pkh,  g_kh);
    cudaGetSymbolAddress((void**)&pkl,  g_kl);
    cudaGetSymbolAddress((void**)&pvh,  g_vh);
    cudaGetSymbolAddress((void**)&pvl,  g_vl);
    cudaGetSymbolAddress((void**)&poh,  g_oh);
    cudaGetSymbolAddress((void**)&pol,  g_ol);
    cudaGetSymbolAddress((void**)&ph1h, g_h1h);
    cudaGetSymbolAddress((void**)&ph1l, g_h1l);

    tsplit_all_kernel<<<12288, 256>>>(Wq, Wk, Wv, Wo, W1, W2, pwth, pwtl);

    embed_kernel<<<ROWS, 128>>>(tok, cnt, emb);

    dim3 gD(Dz / 128, ROWS / 128);
    dim3 gQKV(12, ROWS / 128);
    dim3 gF(DFFz / 128, ROWS / 128);

    for (int l = 0; l < Lz; l++) {
        layernorm_kernel<<<ROWS, 128>>>(px, ln1g + l*Dz, ln1b + l*Dz, pxn, pxnh, pxnl);

        qkv3_kernel<<<gQKV, 128, GSMEM>>>(pxnh, pxnl,
            pwth + OFF_WQ + (size_t)l*DD, pwtl + OFF_WQ + (size_t)l*DD,
            pwth + OFF_WK + (size_t)l*DD, pwtl + OFF_WK + (size_t)l*DD,
            pwth + OFF_WV + (size_t)l*DD, pwtl + OFF_WV + (size_t)l*DD,
            bq + l*Dz, bk + l*Dz, bv + l*Dz, pqh, pql, pk, pv);

        quantdq_kernel<<<dim3(ROWS * Hz / 8, 2), 256>>>(
            pk, pv, pkh, pkl, pvh, pvl,
            cbk + (size_t)(l*2 + 0)*8, cbk + (size_t)(l*2 + 1)*8);

        attn2_kernel<<<dim3(8, Bz*Hz), 128, ATTN2_SMEM>>>(
            pqh, pql, pkh, pkl, pvh, pvl, poh, pol, pcb, pkeep);

        gemm3_kernel<2><<<gD, 128, GSMEM>>>(ROWS, Dz, Dz, poh, pol,
            pwth + OFF_WO + (size_t)l*DD, pwtl + OFF_WO + (size_t)l*DD,
            bo + l*Dz, pxn, px, nullptr, nullptr, 0);

        layernorm_kernel<<<ROWS, 128>>>(px, ln2g + l*Dz, ln2b + l*Dz, pxn, pxnh, pxnl);

        gemm3_kernel<1><<<gF, 128, GSMEM>>>(ROWS, DFFz, Dz, pxnh, pxnl,
            pwth + OFF_W1 + (size_t)l*DF, pwtl + OFF_W1 + (size_t)l*DF,
            b1 + l*DFFz, nullptr, nullptr, ph1h, ph1l, 1);

        float* dst = (l == Lz - 1) ? out : px;
        gemm3_kernel<2><<<gD, 128, GSMEM>>>(ROWS, Dz, DFFz, ph1h, ph1l,
            pwth + OFF_W2 + (size_t)l*DF, pwtl + OFF_W2 + (size_t)l*DF,
            b2 + l*Dz, pxn, dst, nullptr, nullptr, 0);
    }
}